// round 5
// baseline (speedup 1.0000x reference)
#include <cuda_runtime.h>
#include <math.h>

// Problem constants (fixed shapes for this bench)
#define S   2048
#define H   2048
#define ROOM 256
#define NH  16
#define HD  128
#define SCALE 0.08838834764831845f  // 1/sqrt(128)

// Scratch (allocation-free rule: __device__ globals)
__device__ float g_Q[(size_t)S * H];     // 16 MB  Q projection [S, H]
__device__ float g_K[(size_t)S * ROOM];  //  2 MB  k_one [S, 256]
__device__ float g_V[(size_t)S * ROOM];  //  2 MB  v_one [S, 256]
__device__ float g_A[(size_t)S * H];     // 16 MB  attn_out [S, H]
__device__ int   g_rooms[8];             // canonical active_rooms (int)

// GEMM tiling
#define BM 128
#define BN 128
#define BK 8
#define LDS_PAD 4
#define LD  (BM + LDS_PAD)   // 132, keeps float4 alignment, conflict-free fill

// ---------------------------------------------------------------------------
// active_rooms may arrive as int32 (JAX default: int64 silently downgraded)
// or as genuine int64. Detect from the first 8 words:
//   int64 arange -> words [0,0,1,0,2,0,3,0]  (odd words all zero)
//   int32 arange -> words [0,1,2,3,4,5,6,7]
// Only reads words 8..15 when int64 was detected (buffer is 64B then).
// ---------------------------------------------------------------------------
__global__ void normalize_rooms_kernel(const int* __restrict__ w)
{
    bool is64 = (w[1] == 0) && (w[3] == 0) && (w[5] == 0) && (w[7] == 0);
    for (int i = 0; i < 8; i++)
        g_rooms[i] = is64 ? w[2 * i] : w[i];
}

// ---------------------------------------------------------------------------
// NT body: C[M,N] = A[M,K] @ B[N,K]^T   (row-major, K contiguous in both)
// Optional 256-row-block gather on B rows via `rooms`.
// ---------------------------------------------------------------------------
__device__ __forceinline__ void nt_tile(
    const float* __restrict__ A, int lda,
    const float* __restrict__ B, int ldb,
    float* __restrict__ C, int ldc,
    int K, int m0, int n0, float scale,
    const int* __restrict__ rooms)
{
    __shared__ float As[BK][LD];
    __shared__ float Bs[BK][LD];
    const int tid = threadIdx.x;
    const int ty = tid >> 4, tx = tid & 15;

    float acc[8][8];
#pragma unroll
    for (int i = 0; i < 8; i++)
#pragma unroll
        for (int j = 0; j < 8; j++) acc[i][j] = 0.f;

    for (int kk = 0; kk < K; kk += BK) {
#pragma unroll
        for (int i = 0; i < 4; i++) {
            int idx = tid + i * 256;          // 0..1023
            int r = idx >> 3, c = idx & 7;    // r: 0..127, c: 0..7
            As[c][r] = A[(size_t)(m0 + r) * lda + kk + c];
            int n = n0 + r;
            int src = rooms ? rooms[n >> 8] * ROOM + (n & (ROOM - 1)) : n;
            Bs[c][r] = B[(size_t)src * ldb + kk + c];
        }
        __syncthreads();
#pragma unroll
        for (int k = 0; k < BK; k++) {
            float a[8], b[8];
            *(float4*)(a)     = *(const float4*)&As[k][ty * 8];
            *(float4*)(a + 4) = *(const float4*)&As[k][ty * 8 + 4];
            *(float4*)(b)     = *(const float4*)&Bs[k][tx * 8];
            *(float4*)(b + 4) = *(const float4*)&Bs[k][tx * 8 + 4];
#pragma unroll
            for (int i = 0; i < 8; i++)
#pragma unroll
                for (int j = 0; j < 8; j++) acc[i][j] = fmaf(a[i], b[j], acc[i][j]);
        }
        __syncthreads();
    }

#pragma unroll
    for (int i = 0; i < 8; i++)
#pragma unroll
        for (int j = 0; j < 8; j++)
            C[(size_t)(m0 + ty * 8 + i) * ldc + (n0 + tx * 8 + j)] = acc[i][j] * scale;
}

// ---------------------------------------------------------------------------
// NN body: C[M,N] = A[M,K] @ B[K,N]   (row-major)
// Optional 256-row-block gather on B rows (k index) via `rooms`.
// ---------------------------------------------------------------------------
__device__ __forceinline__ void nn_tile(
    const float* __restrict__ A, int lda,
    const float* __restrict__ B, int ldb,
    float* __restrict__ C, int ldc,
    int K, int m0, int n0,
    const int* __restrict__ rooms)
{
    __shared__ float As[BK][LD];
    __shared__ float Bs[BK][LD];
    const int tid = threadIdx.x;
    const int ty = tid >> 4, tx = tid & 15;

    float acc[8][8];
#pragma unroll
    for (int i = 0; i < 8; i++)
#pragma unroll
        for (int j = 0; j < 8; j++) acc[i][j] = 0.f;

    for (int kk = 0; kk < K; kk += BK) {
#pragma unroll
        for (int i = 0; i < 4; i++) {
            int idx = tid + i * 256;
            int r = idx >> 3, c = idx & 7;
            As[c][r] = A[(size_t)(m0 + r) * lda + kk + c];
            int kr = idx >> 7, n = idx & 127;   // kr: 0..7, n: 0..127
            int krow = kk + kr;
            int src = rooms ? rooms[krow >> 8] * ROOM + (krow & (ROOM - 1)) : krow;
            Bs[kr][n] = B[(size_t)src * ldb + n0 + n];
        }
        __syncthreads();
#pragma unroll
        for (int k = 0; k < BK; k++) {
            float a[8], b[8];
            *(float4*)(a)     = *(const float4*)&As[k][ty * 8];
            *(float4*)(a + 4) = *(const float4*)&As[k][ty * 8 + 4];
            *(float4*)(b)     = *(const float4*)&Bs[k][tx * 8];
            *(float4*)(b + 4) = *(const float4*)&Bs[k][tx * 8 + 4];
#pragma unroll
            for (int i = 0; i < 8; i++)
#pragma unroll
                for (int j = 0; j < 8; j++) acc[i][j] = fmaf(a[i], b[j], acc[i][j]);
        }
        __syncthreads();
    }

#pragma unroll
    for (int i = 0; i < 8; i++)
#pragma unroll
        for (int j = 0; j < 8; j++)
            C[(size_t)(m0 + ty * 8 + i) * ldc + (n0 + tx * 8 + j)] = acc[i][j];
}

// ---------------------------------------------------------------------------
// Kernels
// ---------------------------------------------------------------------------

// Q projection: g_Q[s, n] = hidden[s,:] . q_block[map(n), :]
__global__ __launch_bounds__(256) void proj_q_kernel(
    const float* __restrict__ hidden, const float* __restrict__ qb)
{
    nt_tile(hidden, H, qb, H, g_Q, H, H,
            blockIdx.y * BM, blockIdx.x * BN, 1.0f, g_rooms);
}

// K/V projection (z=0 -> K, z=1 -> V)
__global__ __launch_bounds__(256) void proj_kv_kernel(
    const float* __restrict__ hidden,
    const float* __restrict__ kb, const float* __restrict__ vb)
{
    const float* B = (blockIdx.z == 0) ? kb : vb;
    float* C = (blockIdx.z == 0) ? g_K : g_V;
    nt_tile(hidden, H, B, H, C, ROOM, H,
            blockIdx.y * BM, blockIdx.x * BN, 1.0f, nullptr);
}

// scores (raw, scaled): W[h, q, k] = (Qh[q,:] . Kh[k,:]) * SCALE, lower-tri tiles only
__global__ __launch_bounds__(256) void scores_kernel(float* __restrict__ W)
{
    const int h = blockIdx.z;
    const int m0 = blockIdx.y * BM, n0 = blockIdx.x * BN;
    if (n0 >= m0 + BM) return;  // strictly above diagonal -> all masked
    nt_tile(g_Q + (size_t)h * HD, H,
            g_K + (size_t)(h & 1) * HD, ROOM,
            W + (size_t)h * S * S, S,
            HD, m0, n0, SCALE, nullptr);
}

// softmax per (head, query row); writes normalized weights, zeros above diagonal
__global__ __launch_bounds__(256) void softmax_kernel(float* __restrict__ W)
{
    const int q = blockIdx.x, h = blockIdx.y;
    float* row = W + ((size_t)h * S + q) * S;
    const int L = q + 1;
    const int tid = threadIdx.x;
    __shared__ float sh[8];

    // max
    float m = -3.4e38f;
    for (int k = tid; k < L; k += 256) m = fmaxf(m, row[k]);
#pragma unroll
    for (int o = 16; o > 0; o >>= 1) m = fmaxf(m, __shfl_xor_sync(0xffffffffu, m, o));
    if ((tid & 31) == 0) sh[tid >> 5] = m;
    __syncthreads();
    float mm = sh[0];
#pragma unroll
    for (int i = 1; i < 8; i++) mm = fmaxf(mm, sh[i]);
    __syncthreads();

    // sum
    float s = 0.f;
    for (int k = tid; k < L; k += 256) s += __expf(row[k] - mm);
#pragma unroll
    for (int o = 16; o > 0; o >>= 1) s += __shfl_xor_sync(0xffffffffu, s, o);
    if ((tid & 31) == 0) sh[tid >> 5] = s;
    __syncthreads();
    float ssum = 0.f;
#pragma unroll
    for (int i = 0; i < 8; i++) ssum += sh[i];
    const float inv = 1.0f / ssum;

    // write
    for (int k = tid; k < L; k += 256) row[k] = __expf(row[k] - mm) * inv;
    for (int k = L + tid; k < S; k += 256) row[k] = 0.f;
}

// AV: g_A[q, h*128 + d] = sum_k W[h,q,k] * Vh[k, d]   (K loop causal-limited)
__global__ __launch_bounds__(256) void av_kernel(const float* __restrict__ W)
{
    const int h = blockIdx.z;
    const int m0 = blockIdx.y * BM;
    int Keff = m0 + BM;           // weights are 0 beyond the query tile's diagonal
    if (Keff > S) Keff = S;
    nn_tile(W + (size_t)h * S * S, S,
            g_V + (size_t)(h & 1) * HD, ROOM,
            g_A + (size_t)h * HD, H,
            Keff, m0, 0, nullptr);
}

// O projection: out[s, hcol] = sum_t g_A[s, t] * o_block[map(t), hcol]
__global__ __launch_bounds__(256) void oproj_kernel(
    const float* __restrict__ ob, float* __restrict__ out)
{
    nn_tile(g_A, H, ob, H, out, H, H,
            blockIdx.y * BM, blockIdx.x * BN, g_rooms);
}

// ---------------------------------------------------------------------------
// Launch
// ---------------------------------------------------------------------------
extern "C" void kernel_launch(void* const* d_in, const int* in_sizes, int n_in,
                              void* d_out, int out_size)
{
    const float* hidden = (const float*)d_in[0];        // [1, S, H]
    const float* qb     = (const float*)d_in[1];        // [H, H]
    const float* kb     = (const float*)d_in[2];        // [ROOM, H]
    const float* vb     = (const float*)d_in[3];        // [ROOM, H]
    const float* ob     = (const float*)d_in[4];        // [H, H]
    const int*   rooms_raw = (const int*)d_in[5];       // [8] int32 or int64

    float* out   = (float*)d_out;
    float* o_out = out;                         // [S, H]
    float* W     = out + (size_t)S * H;         // [NH, S, S] attn weights

    (void)in_sizes; (void)n_in; (void)out_size;

    // 0) canonicalize active_rooms (int32 vs int64 layout)
    normalize_rooms_kernel<<<1, 1>>>(rooms_raw);

    // 1) Q projection (gathered rows of q_block)
    proj_q_kernel<<<dim3(H / BN, S / BM), 256>>>(hidden, qb);

    // 2) K and V projections (single 256-wide block each)
    proj_kv_kernel<<<dim3(ROOM / BN, S / BM, 2), 256>>>(hidden, kb, vb);

    // 3) scores (raw, scaled, lower-triangular tiles)
    scores_kernel<<<dim3(S / BN, S / BM, NH), 256>>>(W);

    // 4) softmax (normalized weights, exact zeros above diagonal)
    softmax_kernel<<<dim3(S, NH), 256>>>(W);

    // 5) AV
    av_kernel<<<dim3(1, S / BM, NH), 256>>>(W);

    // 6) O projection (gathered rows of o_block)
    oproj_kernel<<<dim3(H / BN, S / BM), 256>>>(ob, o_out);
}

// round 6
// speedup vs baseline: 3.5613x; 3.5613x over previous
#include <cuda_runtime.h>
#include <cuda_bf16.h>
#include <math.h>

// Problem constants (fixed shapes for this bench)
#define S   2048
#define H   2048
#define ROOM 256
#define NH  16
#define HD  128
#define SCALE 0.08838834764831845f  // 1/sqrt(128)

// Scratch (allocation-free rule: __device__ globals)
__device__ float g_Q[(size_t)S * H];     // 16 MB  Q projection [S, H]
__device__ float g_K[(size_t)S * ROOM];  //  2 MB  k_one [S, 256]
__device__ float g_V[(size_t)S * ROOM];  //  2 MB  v_one [S, 256]
__device__ float g_A[(size_t)S * H];     // 16 MB  attn_out [S, H]
__device__ int   g_rooms[8];             // canonical active_rooms

// GEMM tiling
#define BM 128
#define BN 128
#define BK 32

// ---------------------------------------------------------------------------
// active_rooms may arrive as int32 (JAX default x64-disabled downgrade) or
// int64. Detect from first 8 words; only read words 8..15 if int64.
// ---------------------------------------------------------------------------
__global__ void normalize_rooms_kernel(const int* __restrict__ w)
{
    bool is64 = (w[1] == 0) && (w[3] == 0) && (w[5] == 0) && (w[7] == 0);
    for (int i = 0; i < 8; i++)
        g_rooms[i] = is64 ? w[2 * i] : w[i];
}

// ---------------------------------------------------------------------------
// bf16 split helpers:  x = hi + lo  (lo = bf16(x - bf16(x)))
// Packs two consecutive elements into one u32 (low 16 bits = first element).
// ---------------------------------------------------------------------------
__device__ __forceinline__ void split2(float2 v, unsigned &h, unsigned &l)
{
    __nv_bfloat16 h0 = __float2bfloat16_rn(v.x);
    __nv_bfloat16 h1 = __float2bfloat16_rn(v.y);
    float r0 = v.x - __bfloat162float(h0);
    float r1 = v.y - __bfloat162float(h1);
    __nv_bfloat16 l0 = __float2bfloat16_rn(r0);
    __nv_bfloat16 l1 = __float2bfloat16_rn(r1);
    h = ((unsigned)__bfloat16_as_ushort(h1) << 16) | __bfloat16_as_ushort(h0);
    l = ((unsigned)__bfloat16_as_ushort(l1) << 16) | __bfloat16_as_ushort(l0);
}

__device__ __forceinline__ void mma16816(float* d, const unsigned* a, const unsigned* b)
{
    asm volatile(
        "mma.sync.aligned.m16n8k16.row.col.f32.bf16.bf16.f32 "
        "{%0,%1,%2,%3}, {%4,%5,%6,%7}, {%8,%9}, {%0,%1,%2,%3};\n"
        : "+f"(d[0]), "+f"(d[1]), "+f"(d[2]), "+f"(d[3])
        : "r"(a[0]), "r"(a[1]), "r"(a[2]), "r"(a[3]), "r"(b[0]), "r"(b[1]));
}

// ---------------------------------------------------------------------------
// Tensor-core block GEMM, fp32 in / fp32 out, bf16 2-term split (3 MMAs).
//   NT = true :  C[M,N] = A[M,K] @ B[N,K]^T   (both row-major, K contiguous)
//   NT = false:  C[M,N] = A[M,K] @ B[K,N]
//   GATHER: NT -> 256-row-block gather on B's n rows; NN -> on B's k rows.
// Block 128x128x32, 256 threads, 8 warps of 64x32.
// Smem tiles stored in MMA-fragment order (LDS.128/LDS.64 per fragment).
// ---------------------------------------------------------------------------
template<bool NT, bool GATHER>
__device__ __forceinline__ void mma_gemm(
    const float* __restrict__ A, int lda,
    const float* __restrict__ B, int ldb,
    float* __restrict__ C, int ldc,
    int K, int m0, int n0, float scale)
{
    __shared__ unsigned sAh[2048], sAl[2048], sBh[2048], sBl[2048];
    const int tid = threadIdx.x;
    const int ln  = tid & 31;
    const int warp = tid >> 5;
    const int wm = warp >> 2, wn = warp & 3;   // warp grid 2 x 4

    // ---- staging address precompute (A: row-major M x K, pairs along k) ----
    int a_soff[8], a_goff[8];
#pragma unroll
    for (int i = 0; i < 8; i++) {
        int linear = tid + 256 * i;            // 0..2047 pairs
        int r = linear >> 4, c = (linear & 15) * 2;
        int rr = r & 15, cc = c & 15;
        a_soff[i] = (((r >> 4) * 2 + (c >> 4)) * 32
                     + (rr & 7) * 4 + ((cc & 7) >> 1)) * 4
                    + ((rr >> 3) | ((cc >> 3) << 1));
        a_goff[i] = (m0 + r) * lda + c;
    }

    // ---- B staging precompute ----
    int b_soff[8], b_aux[8];                   // NT: gmem offset; NN: n column
#pragma unroll
    for (int i = 0; i < 8; i++) {
        int linear = tid + 256 * i;
        if (NT) {
            int nn = linear >> 4, kk = (linear & 15) * 2;
            int k16 = kk & 15;
            b_soff[i] = (((nn >> 3) * 2 + (kk >> 4)) * 32
                         + (nn & 7) * 4 + ((k16 & 7) >> 1)) * 2
                        + (k16 >> 3);
            int row = n0 + nn;
            if (GATHER) row = g_rooms[row >> 8] * ROOM + (row & 255);
            b_aux[i] = row * ldb + kk;
        } else {
            int kk = (linear >> 7) * 2, nn = linear & 127;
            int k16 = kk & 15;
            b_soff[i] = (((nn >> 3) * 2 + (kk >> 4)) * 32
                         + (nn & 7) * 4 + ((k16 & 7) >> 1)) * 2
                        + (k16 >> 3);
            b_aux[i] = n0 + nn;
        }
    }

    float acc[4][4][4];
#pragma unroll
    for (int i = 0; i < 4; i++)
#pragma unroll
        for (int j = 0; j < 4; j++)
#pragma unroll
            for (int r = 0; r < 4; r++) acc[i][j][r] = 0.f;

    float2 pa[8], pb[8];

    // ---- preload tile kk=0 ----
#pragma unroll
    for (int i = 0; i < 8; i++) pa[i] = *(const float2*)(A + a_goff[i]);
#pragma unroll
    for (int i = 0; i < 8; i++) {
        if (NT) {
            pb[i] = *(const float2*)(B + b_aux[i]);
        } else {
            int kk = ((tid + 256 * i) >> 7) * 2;
            int r0 = kk, r1 = kk + 1;
            if (GATHER) {
                r0 = g_rooms[r0 >> 8] * ROOM + (r0 & 255);
                r1 = g_rooms[r1 >> 8] * ROOM + (r1 & 255);
            }
            pb[i].x = B[(size_t)r0 * ldb + b_aux[i]];
            pb[i].y = B[(size_t)r1 * ldb + b_aux[i]];
        }
    }

    for (int kk = 0; kk < K; kk += BK) {
        // convert + store current tile
#pragma unroll
        for (int i = 0; i < 8; i++) {
            unsigned h, l;
            split2(pa[i], h, l);
            sAh[a_soff[i]] = h; sAl[a_soff[i]] = l;
            split2(pb[i], h, l);
            sBh[b_soff[i]] = h; sBl[b_soff[i]] = l;
        }
        __syncthreads();

        // prefetch next tile
        if (kk + BK < K) {
            int kn = kk + BK;
#pragma unroll
            for (int i = 0; i < 8; i++) pa[i] = *(const float2*)(A + a_goff[i] + kn);
#pragma unroll
            for (int i = 0; i < 8; i++) {
                if (NT) {
                    pb[i] = *(const float2*)(B + b_aux[i] + kn);
                } else {
                    int kr = kn + ((tid + 256 * i) >> 7) * 2;
                    int r0 = kr, r1 = kr + 1;
                    if (GATHER) {
                        r0 = g_rooms[r0 >> 8] * ROOM + (r0 & 255);
                        r1 = g_rooms[r1 >> 8] * ROOM + (r1 & 255);
                    }
                    pb[i].x = B[(size_t)r0 * ldb + b_aux[i]];
                    pb[i].y = B[(size_t)r1 * ldb + b_aux[i]];
                }
            }
        }

        // compute on smem tile
#pragma unroll
        for (int ks = 0; ks < 2; ks++) {
            unsigned bh[4][2], bl[4][2];
#pragma unroll
            for (int j = 0; j < 4; j++) {
                int base = (((wn * 4 + j) * 2 + ks) * 32 + ln) * 2;
                *(uint2*)bh[j] = *(const uint2*)&sBh[base];
                *(uint2*)bl[j] = *(const uint2*)&sBl[base];
            }
#pragma unroll
            for (int i = 0; i < 4; i++) {
                int abase = (((wm * 4 + i) * 2 + ks) * 32 + ln) * 4;
                unsigned ah[4], al[4];
                *(uint4*)ah = *(const uint4*)&sAh[abase];
                *(uint4*)al = *(const uint4*)&sAl[abase];
#pragma unroll
                for (int j = 0; j < 4; j++) {
                    mma16816(acc[i][j], ah, bh[j]);
                    mma16816(acc[i][j], ah, bl[j]);
                    mma16816(acc[i][j], al, bh[j]);
                }
            }
        }
        __syncthreads();
    }

    // ---- epilogue ----
    const int g = ln >> 2, t = ln & 3;
#pragma unroll
    for (int i = 0; i < 4; i++) {
        int row = m0 + wm * 64 + i * 16 + g;
#pragma unroll
        for (int j = 0; j < 4; j++) {
            int col = n0 + wn * 32 + j * 8 + t * 2;
            *(float2*)&C[(size_t)row * ldc + col] =
                make_float2(acc[i][j][0] * scale, acc[i][j][1] * scale);
            *(float2*)&C[(size_t)(row + 8) * ldc + col] =
                make_float2(acc[i][j][2] * scale, acc[i][j][3] * scale);
        }
    }
}

// ---------------------------------------------------------------------------
// Kernels
// ---------------------------------------------------------------------------

// Q projection: g_Q[s, n] = hidden[s,:] . q_block[map(n), :]
__global__ __launch_bounds__(256) void proj_q_kernel(
    const float* __restrict__ hidden, const float* __restrict__ qb)
{
    mma_gemm<true, true>(hidden, H, qb, H, g_Q, H, H,
                         blockIdx.y * BM, blockIdx.x * BN, 1.0f);
}

// K/V projection (z=0 -> K, z=1 -> V)
__global__ __launch_bounds__(256) void proj_kv_kernel(
    const float* __restrict__ hidden,
    const float* __restrict__ kb, const float* __restrict__ vb)
{
    const float* B = (blockIdx.z == 0) ? kb : vb;
    float* C = (blockIdx.z == 0) ? g_K : g_V;
    mma_gemm<true, false>(hidden, H, B, H, C, ROOM, H,
                          blockIdx.y * BM, blockIdx.x * BN, 1.0f);
}

// scores: W[h, q, k] = (Qh[q,:] . Kh[k,:]) * SCALE, lower-tri tiles only
__global__ __launch_bounds__(256) void scores_kernel(float* __restrict__ W)
{
    const int h = blockIdx.z;
    const int m0 = blockIdx.y * BM, n0 = blockIdx.x * BN;
    if (n0 >= m0 + BM) return;  // strictly above diagonal -> masked
    mma_gemm<true, false>(g_Q + (size_t)h * HD, H,
                          g_K + (size_t)(h & 1) * HD, ROOM,
                          W + (size_t)h * S * S, S,
                          HD, m0, n0, SCALE);
}

// softmax per (head, query row); writes normalized weights, zeros above diag
__global__ __launch_bounds__(256) void softmax_kernel(float* __restrict__ W)
{
    const int q = blockIdx.x, h = blockIdx.y;
    float* row = W + ((size_t)h * S + q) * S;
    const int L = q + 1;
    const int tid = threadIdx.x;
    __shared__ float sh[8];

    float m = -3.4e38f;
    for (int k = tid; k < L; k += 256) m = fmaxf(m, row[k]);
#pragma unroll
    for (int o = 16; o > 0; o >>= 1) m = fmaxf(m, __shfl_xor_sync(0xffffffffu, m, o));
    if ((tid & 31) == 0) sh[tid >> 5] = m;
    __syncthreads();
    float mm = sh[0];
#pragma unroll
    for (int i = 1; i < 8; i++) mm = fmaxf(mm, sh[i]);
    __syncthreads();

    float s = 0.f;
    for (int k = tid; k < L; k += 256) s += __expf(row[k] - mm);
#pragma unroll
    for (int o = 16; o > 0; o >>= 1) s += __shfl_xor_sync(0xffffffffu, s, o);
    if ((tid & 31) == 0) sh[tid >> 5] = s;
    __syncthreads();
    float ssum = 0.f;
#pragma unroll
    for (int i = 0; i < 8; i++) ssum += sh[i];
    const float inv = 1.0f / ssum;

    for (int k = tid; k < L; k += 256) row[k] = __expf(row[k] - mm) * inv;
    for (int k = L + tid; k < S; k += 256) row[k] = 0.f;
}

// AV: g_A[q, h*128 + d] = sum_k W[h,q,k] * Vh[k, d]   (K causal-limited)
__global__ __launch_bounds__(256) void av_kernel(const float* __restrict__ W)
{
    const int h = blockIdx.z;
    const int m0 = blockIdx.y * BM;
    int Keff = m0 + BM;
    if (Keff > S) Keff = S;
    mma_gemm<false, false>(W + (size_t)h * S * S, S,
                           g_V + (size_t)(h & 1) * HD, ROOM,
                           g_A + (size_t)h * HD, H,
                           Keff, m0, 0, 1.0f);
}

// O projection: out[s, hcol] = sum_t g_A[s, t] * o_block[map(t), hcol]
__global__ __launch_bounds__(256) void oproj_kernel(
    const float* __restrict__ ob, float* __restrict__ out)
{
    mma_gemm<false, true>(g_A, H, ob, H, out, H, H,
                          blockIdx.y * BM, blockIdx.x * BN, 1.0f);
}

// ---------------------------------------------------------------------------
// Launch
// ---------------------------------------------------------------------------
extern "C" void kernel_launch(void* const* d_in, const int* in_sizes, int n_in,
                              void* d_out, int out_size)
{
    const float* hidden = (const float*)d_in[0];        // [1, S, H]
    const float* qb     = (const float*)d_in[1];        // [H, H]
    const float* kb     = (const float*)d_in[2];        // [ROOM, H]
    const float* vb     = (const float*)d_in[3];        // [ROOM, H]
    const float* ob     = (const float*)d_in[4];        // [H, H]
    const int*   rooms_raw = (const int*)d_in[5];       // [8] int32 or int64

    float* out   = (float*)d_out;
    float* o_out = out;                         // [S, H]
    float* W     = out + (size_t)S * H;         // [NH, S, S] attn weights

    (void)in_sizes; (void)n_in; (void)out_size;

    // 0) canonicalize active_rooms
    normalize_rooms_kernel<<<1, 1>>>(rooms_raw);

    // 1) Q projection (gathered rows of q_block)
    proj_q_kernel<<<dim3(H / BN, S / BM), 256>>>(hidden, qb);

    // 2) K and V projections
    proj_kv_kernel<<<dim3(ROOM / BN, S / BM, 2), 256>>>(hidden, kb, vb);

    // 3) scores (raw, scaled, lower-triangular tiles)
    scores_kernel<<<dim3(S / BN, S / BM, NH), 256>>>(W);

    // 4) softmax
    softmax_kernel<<<dim3(S, NH), 256>>>(W);

    // 5) AV
    av_kernel<<<dim3(1, S / BM, NH), 256>>>(W);

    // 6) O projection (gathered rows of o_block)
    oproj_kernel<<<dim3(H / BN, S / BM), 256>>>(ob, o_out);
}